// round 2
// baseline (speedup 1.0000x reference)
#include <cuda_runtime.h>

#define N_NODES 8192
#define DIM 512

// Scratch (allocation-free rule: __device__ globals)
__device__ float g_agg[N_NODES * DIM];    // 16 MB
__device__ float g_A[DIM * DIM];          // W_self @ W_comb[0:512]
__device__ float g_B[DIM * DIM];          // W_nb   @ W_comb[512:1024]
__device__ float g_c[DIM];                // fused bias
__device__ float g_recip[N_NODES];        // 1/max(deg,1)

// ---------------------------------------------------------------------------
// K0a: A = W_self @ W_comb_top ; B = W_nb @ W_comb_bot   (blockIdx.z selects)
// 64x64 tile, 256 threads, 4x4 microtile, BK=16
// ---------------------------------------------------------------------------
__global__ void fuse_weights_kernel(const float* __restrict__ W_self,
                                    const float* __restrict__ W_nb,
                                    const float* __restrict__ W_comb) {
    const int z = blockIdx.z;
    const float* __restrict__ Wx = z ? W_nb : W_self;
    float* __restrict__ out = z ? g_B : g_A;
    const int woff = z * DIM;

    __shared__ float As[16][64];
    __shared__ float Bs[16][64];

    const int tid = threadIdx.x;
    const int tx = tid & 15, ty = tid >> 4;
    const int brow = blockIdx.y * 64;
    const int bcol = blockIdx.x * 64;

    const int a_m  = tid >> 2;
    const int a_kc = (tid & 3) << 2;
    const int b_k  = tid >> 4;
    const int b_n  = (tid & 15) << 2;

    float acc[4][4] = {};

    for (int k0 = 0; k0 < DIM; k0 += 16) {
        float4 av = *(const float4*)&Wx[(brow + a_m) * DIM + k0 + a_kc];
        As[a_kc + 0][a_m] = av.x;
        As[a_kc + 1][a_m] = av.y;
        As[a_kc + 2][a_m] = av.z;
        As[a_kc + 3][a_m] = av.w;
        *(float4*)&Bs[b_k][b_n] =
            *(const float4*)&W_comb[(woff + k0 + b_k) * DIM + bcol + b_n];
        __syncthreads();
        #pragma unroll
        for (int k = 0; k < 16; k++) {
            float af[4], bf[4];
            *(float4*)af = *(const float4*)&As[k][ty * 4];
            *(float4*)bf = *(const float4*)&Bs[k][tx * 4];
            #pragma unroll
            for (int i = 0; i < 4; i++)
                #pragma unroll
                for (int j = 0; j < 4; j++)
                    acc[i][j] += af[i] * bf[j];
        }
        __syncthreads();
    }
    #pragma unroll
    for (int i = 0; i < 4; i++)
        #pragma unroll
        for (int j = 0; j < 4; j++)
            out[(brow + ty * 4 + i) * DIM + bcol + tx * 4 + j] = acc[i][j];
}

// ---------------------------------------------------------------------------
// K0b: c[j] = b_comb[j] + sum_k b_self[k]*Wt[k,j] + b_nb[k]*Wb[k,j]
// ---------------------------------------------------------------------------
__global__ void fuse_bias_kernel(const float* __restrict__ b_self,
                                 const float* __restrict__ b_nb,
                                 const float* __restrict__ W_comb,
                                 const float* __restrict__ b_comb) {
    const int j = threadIdx.x;  // 512 threads, 1 block
    float s0 = b_comb[j], s1 = 0.f, s2 = 0.f, s3 = 0.f;
    #pragma unroll 4
    for (int k = 0; k < DIM; k += 2) {
        s0 += b_self[k]     * W_comb[k * DIM + j];
        s1 += b_self[k + 1] * W_comb[(k + 1) * DIM + j];
        s2 += b_nb[k]       * W_comb[(DIM + k) * DIM + j];
        s3 += b_nb[k + 1]   * W_comb[(DIM + k + 1) * DIM + j];
    }
    g_c[j] = (s0 + s1) + (s2 + s3);
}

// ---------------------------------------------------------------------------
// K1: g_recip[i] = 1 / max(#neighbors(i), 1)
// ---------------------------------------------------------------------------
__global__ void degree_kernel(const int* __restrict__ adj) {
    const int row = blockIdx.x;
    const int4* __restrict__ p = (const int4*)(adj + (size_t)row * N_NODES);
    int cnt = 0;
    for (int i = threadIdx.x; i < N_NODES / 4; i += blockDim.x) {
        int4 v = p[i];
        cnt += (v.x > 0) + (v.y > 0) + (v.z > 0) + (v.w > 0);
    }
    #pragma unroll
    for (int o = 16; o; o >>= 1) cnt += __shfl_down_sync(0xffffffffu, cnt, o);
    __shared__ int wsum[8];
    if ((threadIdx.x & 31) == 0) wsum[threadIdx.x >> 5] = cnt;
    __syncthreads();
    if (threadIdx.x == 0) {
        int t = 0;
        #pragma unroll
        for (int w = 0; w < 8; w++) t += wsum[w];
        g_recip[row] = 1.0f / (float)max(t, 1);
    }
}

// ---------------------------------------------------------------------------
// K2: agg = (mask(adj) @ x) * recip   — M=8192, N=512, K=8192
// 128x128 tile, 256 threads, 8x8 microtile, BK=16
// ---------------------------------------------------------------------------
__global__ void __launch_bounds__(256, 2) agg_gemm_kernel(
    const int* __restrict__ adj, const float* __restrict__ x) {
    __shared__ float As[16][128];
    __shared__ float Bs[16][128];

    const int tid = threadIdx.x;
    const int tx = tid & 15, ty = tid >> 4;
    const int brow = blockIdx.y * 128;
    const int bcol = blockIdx.x * 128;
    const int4* __restrict__ adjv = (const int4*)adj;

    float acc[8][8] = {};

    for (int k0 = 0; k0 < N_NODES; k0 += 16) {
        #pragma unroll
        for (int l = 0; l < 2; l++) {
            const int idx = tid + l * 256;
            const int m  = idx >> 2;
            const int kc = (idx & 3) << 2;
            int4 v = adjv[((size_t)(brow + m) * N_NODES + k0 + kc) >> 2];
            As[kc + 0][m] = v.x > 0 ? 1.0f : 0.0f;
            As[kc + 1][m] = v.y > 0 ? 1.0f : 0.0f;
            As[kc + 2][m] = v.z > 0 ? 1.0f : 0.0f;
            As[kc + 3][m] = v.w > 0 ? 1.0f : 0.0f;
            const int k  = idx >> 5;
            const int n4 = (idx & 31) << 2;
            *(float4*)&Bs[k][n4] =
                *(const float4*)&x[(size_t)(k0 + k) * DIM + bcol + n4];
        }
        __syncthreads();
        #pragma unroll
        for (int k = 0; k < 16; k++) {
            float af[8], bf[8];
            *(float4*)&af[0] = *(const float4*)&As[k][ty * 8];
            *(float4*)&af[4] = *(const float4*)&As[k][ty * 8 + 4];
            *(float4*)&bf[0] = *(const float4*)&Bs[k][tx * 8];
            *(float4*)&bf[4] = *(const float4*)&Bs[k][tx * 8 + 4];
            #pragma unroll
            for (int i = 0; i < 8; i++)
                #pragma unroll
                for (int j = 0; j < 8; j++)
                    acc[i][j] += af[i] * bf[j];
        }
        __syncthreads();
    }
    #pragma unroll
    for (int i = 0; i < 8; i++) {
        const int r = brow + ty * 8 + i;
        const float rc = g_recip[r];
        #pragma unroll
        for (int j = 0; j < 8; j += 4) {
            float4 v = make_float4(acc[i][j] * rc, acc[i][j + 1] * rc,
                                   acc[i][j + 2] * rc, acc[i][j + 3] * rc);
            *(float4*)&g_agg[(size_t)r * DIM + bcol + tx * 8 + j] = v;
        }
    }
}

// ---------------------------------------------------------------------------
// K3: out = relu(x @ g_A + agg @ g_B + g_c)   — M=8192, N=512, K=512 (x2)
// ---------------------------------------------------------------------------
__global__ void __launch_bounds__(256, 2) out_gemm_kernel(
    const float* __restrict__ x, float* __restrict__ out) {
    __shared__ float As[16][128];
    __shared__ float Bs[16][128];

    const int tid = threadIdx.x;
    const int tx = tid & 15, ty = tid >> 4;
    const int brow = blockIdx.y * 128;
    const int bcol = blockIdx.x * 128;

    float acc[8][8] = {};

    #pragma unroll
    for (int pass = 0; pass < 2; pass++) {
        const float* __restrict__ Am = pass ? g_agg : x;
        const float* __restrict__ Wm = pass ? g_B : g_A;
        for (int k0 = 0; k0 < DIM; k0 += 16) {
            #pragma unroll
            for (int l = 0; l < 2; l++) {
                const int idx = tid + l * 256;
                const int m  = idx >> 2;
                const int kc = (idx & 3) << 2;
                float4 av = *(const float4*)&Am[(size_t)(brow + m) * DIM + k0 + kc];
                As[kc + 0][m] = av.x;
                As[kc + 1][m] = av.y;
                As[kc + 2][m] = av.z;
                As[kc + 3][m] = av.w;
                const int k  = idx >> 5;
                const int n4 = (idx & 31) << 2;
                *(float4*)&Bs[k][n4] =
                    *(const float4*)&Wm[(size_t)(k0 + k) * DIM + bcol + n4];
            }
            __syncthreads();
            #pragma unroll
            for (int k = 0; k < 16; k++) {
                float af[8], bf[8];
                *(float4*)&af[0] = *(const float4*)&As[k][ty * 8];
                *(float4*)&af[4] = *(const float4*)&As[k][ty * 8 + 4];
                *(float4*)&bf[0] = *(const float4*)&Bs[k][tx * 8];
                *(float4*)&bf[4] = *(const float4*)&Bs[k][tx * 8 + 4];
                #pragma unroll
                for (int i = 0; i < 8; i++)
                    #pragma unroll
                    for (int j = 0; j < 8; j++)
                        acc[i][j] += af[i] * bf[j];
            }
            __syncthreads();
        }
    }
    float cb[8];
    #pragma unroll
    for (int j = 0; j < 8; j++) cb[j] = g_c[bcol + tx * 8 + j];
    #pragma unroll
    for (int i = 0; i < 8; i++) {
        const int r = brow + ty * 8 + i;
        #pragma unroll
        for (int j = 0; j < 8; j += 4) {
            float4 v;
            v.x = fmaxf(acc[i][j + 0] + cb[j + 0], 0.0f);
            v.y = fmaxf(acc[i][j + 1] + cb[j + 1], 0.0f);
            v.z = fmaxf(acc[i][j + 2] + cb[j + 2], 0.0f);
            v.w = fmaxf(acc[i][j + 3] + cb[j + 3], 0.0f);
            *(float4*)&out[(size_t)r * DIM + bcol + tx * 8 + j] = v;
        }
    }
}

// ---------------------------------------------------------------------------
extern "C" void kernel_launch(void* const* d_in, const int* in_sizes, int n_in,
                              void* d_out, int out_size) {
    const float* x      = (const float*)d_in[0];
    const int*   adj    = (const int*)d_in[1];
    const float* W_self = (const float*)d_in[2];
    const float* b_self = (const float*)d_in[3];
    const float* W_nb   = (const float*)d_in[4];
    const float* b_nb   = (const float*)d_in[5];
    const float* W_comb = (const float*)d_in[6];
    const float* b_comb = (const float*)d_in[7];
    float* out = (float*)d_out;

    fuse_weights_kernel<<<dim3(8, 8, 2), 256>>>(W_self, W_nb, W_comb);
    fuse_bias_kernel<<<1, 512>>>(b_self, b_nb, W_comb, b_comb);
    degree_kernel<<<N_NODES, 256>>>(adj);
    agg_gemm_kernel<<<dim3(DIM / 128, N_NODES / 128), 256>>>(adj, x);
    out_gemm_kernel<<<dim3(DIM / 128, N_NODES / 128), 256>>>(x, out);
}

// round 4
// speedup vs baseline: 2.3927x; 2.3927x over previous
#include <cuda_runtime.h>
#include <cuda_bf16.h>
#include <cstdint>

#define N_NODES 8192
#define DIM 512

// ---------------- scratch (__device__ globals; no allocs allowed) ----------
__device__ float g_agg[N_NODES * DIM];                          // 16 MB
__device__ float g_A[DIM * DIM];                                // W_self@Wt
__device__ float g_B[DIM * DIM];                                // W_nb@Wb
__device__ float g_c[DIM];                                      // fused bias
__device__ float g_recip[N_NODES];                              // 1/max(deg,1)
__device__ __align__(16) __nv_bfloat16 g_xT_hi[DIM * N_NODES];  // 8 MB  [feat][node]
__device__ __align__(16) __nv_bfloat16 g_xT_lo[DIM * N_NODES];  // 8 MB
__device__ __align__(16) __nv_bfloat16 g_mask[(size_t)N_NODES * N_NODES]; // 128 MB

// ---------------- PTX helpers (sm_80-era, safe on plain sm_103 target) -----
__device__ __forceinline__ uint32_t smem_u32(const void* p) {
    uint32_t a;
    asm("{ .reg .u64 t; cvta.to.shared.u64 t, %1; cvt.u32.u64 %0, t; }"
        : "=r"(a) : "l"(p));
    return a;
}
__device__ __forceinline__ void cp16(uint32_t dst, const void* src) {
    asm volatile("cp.async.cg.shared.global [%0], [%1], 16;"
                 :: "r"(dst), "l"(src) : "memory");
}
__device__ __forceinline__ void ldsm4(uint32_t& r0, uint32_t& r1, uint32_t& r2,
                                      uint32_t& r3, uint32_t addr) {
    asm volatile("ldmatrix.sync.aligned.m8n8.x4.shared.b16 {%0,%1,%2,%3}, [%4];"
                 : "=r"(r0), "=r"(r1), "=r"(r2), "=r"(r3) : "r"(addr));
}
__device__ __forceinline__ void mma16816(float* d, const uint32_t* a,
                                         const uint32_t* b) {
    asm volatile(
        "mma.sync.aligned.m16n8k16.row.col.f32.bf16.bf16.f32 "
        "{%0,%1,%2,%3}, {%4,%5,%6,%7}, {%8,%9}, {%0,%1,%2,%3};"
        : "+f"(d[0]), "+f"(d[1]), "+f"(d[2]), "+f"(d[3])
        : "r"(a[0]), "r"(a[1]), "r"(a[2]), "r"(a[3]), "r"(b[0]), "r"(b[1]));
}

// ---------------------------------------------------------------------------
// K0a: A = W_self @ W_comb_top ; B = W_nb @ W_comb_bot
// ---------------------------------------------------------------------------
__global__ void fuse_weights_kernel(const float* __restrict__ W_self,
                                    const float* __restrict__ W_nb,
                                    const float* __restrict__ W_comb) {
    const int z = blockIdx.z;
    const float* __restrict__ Wx = z ? W_nb : W_self;
    float* __restrict__ out = z ? g_B : g_A;
    const int woff = z * DIM;

    __shared__ float As[16][64];
    __shared__ float Bs[16][64];
    const int tid = threadIdx.x;
    const int tx = tid & 15, ty = tid >> 4;
    const int brow = blockIdx.y * 64, bcol = blockIdx.x * 64;
    const int a_m = tid >> 2, a_kc = (tid & 3) << 2;
    const int b_k = tid >> 4, b_n = (tid & 15) << 2;

    float acc[4][4] = {};
    for (int k0 = 0; k0 < DIM; k0 += 16) {
        float4 av = *(const float4*)&Wx[(brow + a_m) * DIM + k0 + a_kc];
        As[a_kc + 0][a_m] = av.x; As[a_kc + 1][a_m] = av.y;
        As[a_kc + 2][a_m] = av.z; As[a_kc + 3][a_m] = av.w;
        *(float4*)&Bs[b_k][b_n] =
            *(const float4*)&W_comb[(woff + k0 + b_k) * DIM + bcol + b_n];
        __syncthreads();
        #pragma unroll
        for (int k = 0; k < 16; k++) {
            float af[4], bf[4];
            *(float4*)af = *(const float4*)&As[k][ty * 4];
            *(float4*)bf = *(const float4*)&Bs[k][tx * 4];
            #pragma unroll
            for (int i = 0; i < 4; i++)
                #pragma unroll
                for (int j = 0; j < 4; j++) acc[i][j] += af[i] * bf[j];
        }
        __syncthreads();
    }
    #pragma unroll
    for (int i = 0; i < 4; i++)
        #pragma unroll
        for (int j = 0; j < 4; j++)
            out[(brow + ty * 4 + i) * DIM + bcol + tx * 4 + j] = acc[i][j];
}

// ---------------------------------------------------------------------------
// K0b: fused bias
// ---------------------------------------------------------------------------
__global__ void fuse_bias_kernel(const float* __restrict__ b_self,
                                 const float* __restrict__ b_nb,
                                 const float* __restrict__ W_comb,
                                 const float* __restrict__ b_comb) {
    const int j = threadIdx.x;
    float s0 = b_comb[j], s1 = 0.f, s2 = 0.f, s3 = 0.f;
    #pragma unroll 4
    for (int k = 0; k < DIM; k += 2) {
        s0 += b_self[k] * W_comb[k * DIM + j];
        s1 += b_self[k + 1] * W_comb[(k + 1) * DIM + j];
        s2 += b_nb[k] * W_comb[(DIM + k) * DIM + j];
        s3 += b_nb[k + 1] * W_comb[(DIM + k + 1) * DIM + j];
    }
    g_c[j] = (s0 + s1) + (s2 + s3);
}

// ---------------------------------------------------------------------------
// K1: degree -> reciprocal, fused with adj -> bf16 mask conversion
// ---------------------------------------------------------------------------
__global__ void degree_mask_kernel(const int* __restrict__ adj) {
    const int row = blockIdx.x;
    const int4* __restrict__ p = (const int4*)(adj + (size_t)row * N_NODES);
    uint2* __restrict__ mrow = (uint2*)(g_mask + (size_t)row * N_NODES);
    int cnt = 0;
    for (int i = threadIdx.x; i < N_NODES / 4; i += blockDim.x) {
        int4 v = p[i];
        cnt += (v.x > 0) + (v.y > 0) + (v.z > 0) + (v.w > 0);
        uint2 o;
        o.x = (v.x > 0 ? 0x3F80u : 0u) | ((v.y > 0 ? 0x3F80u : 0u) << 16);
        o.y = (v.z > 0 ? 0x3F80u : 0u) | ((v.w > 0 ? 0x3F80u : 0u) << 16);
        mrow[i] = o;
    }
    #pragma unroll
    for (int o = 16; o; o >>= 1) cnt += __shfl_down_sync(0xffffffffu, cnt, o);
    __shared__ int wsum[8];
    if ((threadIdx.x & 31) == 0) wsum[threadIdx.x >> 5] = cnt;
    __syncthreads();
    if (threadIdx.x == 0) {
        int t = 0;
        #pragma unroll
        for (int w = 0; w < 8; w++) t += wsum[w];
        g_recip[row] = 1.0f / (float)max(t, 1);
    }
}

// ---------------------------------------------------------------------------
// K1b: transpose x -> bf16 hi/lo, [feature][node] (col-major B for mma)
// ---------------------------------------------------------------------------
__global__ void transpose_split_kernel(const float* __restrict__ x) {
    __shared__ float t[32][33];
    const int c0 = blockIdx.x * 32;   // feature dim
    const int r0 = blockIdx.y * 32;   // node dim
    const int tx = threadIdx.x, ty = threadIdx.y;
    #pragma unroll
    for (int i = 0; i < 4; i++)
        t[ty + 8 * i][tx] = x[(size_t)(r0 + ty + 8 * i) * DIM + c0 + tx];
    __syncthreads();
    #pragma unroll
    for (int i = 0; i < 4; i++) {
        float v = t[tx][ty + 8 * i];
        __nv_bfloat16 h = __float2bfloat16(v);
        __nv_bfloat16 l = __float2bfloat16(v - __bfloat162float(h));
        size_t o = (size_t)(c0 + ty + 8 * i) * N_NODES + r0 + tx;
        g_xT_hi[o] = h;
        g_xT_lo[o] = l;
    }
}

// ---------------------------------------------------------------------------
// K2: agg = (mask @ x) * recip  via HMMA (mma.sync bf16, hi/lo split)
// BM=128, BN=128, BK=32, 4-stage cp.async pipeline, 8 warps (4M x 2N)
// ---------------------------------------------------------------------------
#define BK 32
#define PITCHB 80                 // 40 bf16 per smem row (conflict-free ldmatrix)
#define TILEB (128 * PITCHB)      // 10240 B per tile
#define STAGEB (3 * TILEB)        // A + Bh + Bl
#define STG 4
#define AGG_SMEM (STG * STAGEB)   // 122880 B

__device__ __forceinline__ void issue_stage(uint32_t sb, int slot, int k0,
                                            int brow, int bcol, int tid) {
    const uint32_t base = sb + slot * STAGEB;
    #pragma unroll
    for (int h = 0; h < 2; h++) {
        const int id = tid + h * 256;
        const int row = id >> 2, cc = id & 3;
        const uint32_t so = row * PITCHB + cc * 16;
        const size_t goA = (size_t)(brow + row) * N_NODES + k0 + cc * 8;
        const size_t goB = (size_t)(bcol + row) * N_NODES + k0 + cc * 8;
        cp16(base + so,             g_mask + goA);
        cp16(base + TILEB + so,     g_xT_hi + goB);
        cp16(base + 2 * TILEB + so, g_xT_lo + goB);
    }
    asm volatile("cp.async.commit_group;" ::: "memory");
}

__global__ void __launch_bounds__(256, 1) agg_mma_kernel() {
    extern __shared__ char smem[];
    const uint32_t sb = smem_u32(smem);
    const int tid = threadIdx.x;
    const int lane = tid & 31, w = tid >> 5;
    const int wm = w & 3, wn = w >> 2;
    const int brow = blockIdx.y * 128;
    const int bcol = blockIdx.x * 128;
    const int g = lane >> 3, r = lane & 7;

    const int NIT = N_NODES / BK;  // 256
    issue_stage(sb, 0, 0, brow, bcol, tid);
    issue_stage(sb, 1, BK, brow, bcol, tid);
    issue_stage(sb, 2, 2 * BK, brow, bcol, tid);

    float acc[2][8][4] = {};

    for (int s = 0; s < NIT; s++) {
        asm volatile("cp.async.wait_group 2;" ::: "memory");
        __syncthreads();
        if (s + 3 < NIT)
            issue_stage(sb, (s + 3) & 3, (s + 3) * BK, brow, bcol, tid);
        else
            asm volatile("cp.async.commit_group;" ::: "memory");

        const uint32_t sA  = sb + (s & 3) * STAGEB;
        const uint32_t sBh = sA + TILEB;
        const uint32_t sBl = sA + 2 * TILEB;

        #pragma unroll
        for (int ks = 0; ks < 2; ks++) {
            uint32_t a[2][4];
            #pragma unroll
            for (int mi = 0; mi < 2; mi++) {
                const uint32_t addr = sA +
                    (wm * 32 + mi * 16 + (g & 1) * 8 + r) * PITCHB +
                    ks * 32 + (g >> 1) * 16;
                ldsm4(a[mi][0], a[mi][1], a[mi][2], a[mi][3], addr);
            }
            uint32_t bh[8][2], bl[8][2];
            #pragma unroll
            for (int nj = 0; nj < 4; nj++) {
                const uint32_t roff =
                    (wn * 64 + nj * 16 + (g >> 1) * 8 + r) * PITCHB +
                    ks * 32 + (g & 1) * 16;
                uint32_t r0, r1, r2, r3;
                ldsm4(r0, r1, r2, r3, sBh + roff);
                bh[nj * 2][0] = r0; bh[nj * 2][1] = r1;
                bh[nj * 2 + 1][0] = r2; bh[nj * 2 + 1][1] = r3;
                ldsm4(r0, r1, r2, r3, sBl + roff);
                bl[nj * 2][0] = r0; bl[nj * 2][1] = r1;
                bl[nj * 2 + 1][0] = r2; bl[nj * 2 + 1][1] = r3;
            }
            #pragma unroll
            for (int mi = 0; mi < 2; mi++)
                #pragma unroll
                for (int ni = 0; ni < 8; ni++) {
                    mma16816(acc[mi][ni], a[mi], bh[ni]);
                    mma16816(acc[mi][ni], a[mi], bl[ni]);
                }
        }
    }
    asm volatile("cp.async.wait_group 0;" ::: "memory");

    // epilogue: scale by reciprocal degree, store fp32
    #pragma unroll
    for (int mi = 0; mi < 2; mi++) {
        const int r0 = brow + wm * 32 + mi * 16 + (lane >> 2);
        const float rc0 = g_recip[r0];
        const float rc1 = g_recip[r0 + 8];
        #pragma unroll
        for (int ni = 0; ni < 8; ni++) {
            const int col = bcol + wn * 64 + ni * 8 + (lane & 3) * 2;
            float2 v0 = make_float2(acc[mi][ni][0] * rc0, acc[mi][ni][1] * rc0);
            *(float2*)&g_agg[(size_t)r0 * DIM + col] = v0;
            float2 v1 = make_float2(acc[mi][ni][2] * rc1, acc[mi][ni][3] * rc1);
            *(float2*)&g_agg[(size_t)(r0 + 8) * DIM + col] = v1;
        }
    }
}

// ---------------------------------------------------------------------------
// K3: out = relu(x @ g_A + agg @ g_B + g_c)
// ---------------------------------------------------------------------------
__global__ void __launch_bounds__(256, 2) out_gemm_kernel(
    const float* __restrict__ x, float* __restrict__ out) {
    __shared__ float As[16][128];
    __shared__ float Bs[16][128];
    const int tid = threadIdx.x;
    const int tx = tid & 15, ty = tid >> 4;
    const int brow = blockIdx.y * 128, bcol = blockIdx.x * 128;

    float acc[8][8] = {};
    #pragma unroll
    for (int pass = 0; pass < 2; pass++) {
        const float* __restrict__ Am = pass ? g_agg : x;
        const float* __restrict__ Wm = pass ? g_B : g_A;
        for (int k0 = 0; k0 < DIM; k0 += 16) {
            #pragma unroll
            for (int l = 0; l < 2; l++) {
                const int idx = tid + l * 256;
                const int m = idx >> 2, kc = (idx & 3) << 2;
                float4 av = *(const float4*)&Am[(size_t)(brow + m) * DIM + k0 + kc];
                As[kc + 0][m] = av.x; As[kc + 1][m] = av.y;
                As[kc + 2][m] = av.z; As[kc + 3][m] = av.w;
                const int k = idx >> 5, n4 = (idx & 31) << 2;
                *(float4*)&Bs[k][n4] =
                    *(const float4*)&Wm[(size_t)(k0 + k) * DIM + bcol + n4];
            }
            __syncthreads();
            #pragma unroll
            for (int k = 0; k < 16; k++) {
                float af[8], bf[8];
                *(float4*)&af[0] = *(const float4*)&As[k][ty * 8];
                *(float4*)&af[4] = *(const float4*)&As[k][ty * 8 + 4];
                *(float4*)&bf[0] = *(const float4*)&Bs[k][tx * 8];
                *(float4*)&bf[4] = *(const float4*)&Bs[k][tx * 8 + 4];
                #pragma unroll
                for (int i = 0; i < 8; i++)
                    #pragma unroll
                    for (int j = 0; j < 8; j++) acc[i][j] += af[i] * bf[j];
            }
            __syncthreads();
        }
    }
    float cb[8];
    #pragma unroll
    for (int j = 0; j < 8; j++) cb[j] = g_c[bcol + tx * 8 + j];
    #pragma unroll
    for (int i = 0; i < 8; i++) {
        const int rr = brow + ty * 8 + i;
        #pragma unroll
        for (int j = 0; j < 8; j += 4) {
            float4 v;
            v.x = fmaxf(acc[i][j + 0] + cb[j + 0], 0.0f);
            v.y = fmaxf(acc[i][j + 1] + cb[j + 1], 0.0f);
            v.z = fmaxf(acc[i][j + 2] + cb[j + 2], 0.0f);
            v.w = fmaxf(acc[i][j + 3] + cb[j + 3], 0.0f);
            *(float4*)&out[(size_t)rr * DIM + bcol + tx * 8 + j] = v;
        }
    }
}

// ---------------------------------------------------------------------------
extern "C" void kernel_launch(void* const* d_in, const int* in_sizes, int n_in,
                              void* d_out, int out_size) {
    const float* x      = (const float*)d_in[0];
    const int*   adj    = (const int*)d_in[1];
    const float* W_self = (const float*)d_in[2];
    const float* b_self = (const float*)d_in[3];
    const float* W_nb   = (const float*)d_in[4];
    const float* b_nb   = (const float*)d_in[5];
    const float* W_comb = (const float*)d_in[6];
    const float* b_comb = (const float*)d_in[7];
    float* out = (float*)d_out;

    static bool attr_done = false;
    if (!attr_done) {
        cudaFuncSetAttribute(agg_mma_kernel,
                             cudaFuncAttributeMaxDynamicSharedMemorySize, AGG_SMEM);
        attr_done = true;
    }

    fuse_weights_kernel<<<dim3(8, 8, 2), 256>>>(W_self, W_nb, W_comb);
    fuse_bias_kernel<<<1, 512>>>(b_self, b_nb, W_comb, b_comb);
    degree_mask_kernel<<<N_NODES, 256>>>(adj);
    transpose_split_kernel<<<dim3(DIM / 32, N_NODES / 32), dim3(32, 8)>>>(x);
    agg_mma_kernel<<<dim3(4, 64), 256, AGG_SMEM>>>();
    out_gemm_kernel<<<dim3(DIM / 128, N_NODES / 128), 256>>>(x, out);
}

// round 5
// speedup vs baseline: 2.7983x; 1.1695x over previous
#include <cuda_runtime.h>
#include <cuda_bf16.h>
#include <cstdint>

#define N_NODES 8192
#define DIM 512

// ---------------- scratch (__device__ globals; no allocs allowed) ----------
__device__ float g_c[DIM];                                      // fused bias
__device__ float g_recip[N_NODES];                              // 1/max(deg,1)
__device__ __align__(16) __nv_bfloat16 g_xT_hi[DIM * N_NODES];  // [feat][node]
__device__ __align__(16) __nv_bfloat16 g_xT_lo[DIM * N_NODES];
__device__ __align__(16) __nv_bfloat16 g_x_hi[N_NODES * DIM];   // [node][feat]
__device__ __align__(16) __nv_bfloat16 g_x_lo[N_NODES * DIM];
__device__ __align__(16) __nv_bfloat16 g_agg_hi[N_NODES * DIM]; // [node][feat]
__device__ __align__(16) __nv_bfloat16 g_agg_lo[N_NODES * DIM];
__device__ __align__(16) __nv_bfloat16 g_AT_hi[DIM * DIM];      // [out][in] (W_self@Wt)^T
__device__ __align__(16) __nv_bfloat16 g_AT_lo[DIM * DIM];
__device__ __align__(16) __nv_bfloat16 g_BT_hi[DIM * DIM];      // (W_nb@Wb)^T
__device__ __align__(16) __nv_bfloat16 g_BT_lo[DIM * DIM];
__device__ __align__(16) __nv_bfloat16 g_mask[(size_t)N_NODES * N_NODES]; // 128 MB

// ---------------- PTX helpers (sm_80-era; legal on plain sm_103 target) ----
__device__ __forceinline__ uint32_t smem_u32(const void* p) {
    uint32_t a;
    asm("{ .reg .u64 t; cvta.to.shared.u64 t, %1; cvt.u32.u64 %0, t; }"
        : "=r"(a) : "l"(p));
    return a;
}
__device__ __forceinline__ void cp16(uint32_t dst, const void* src) {
    asm volatile("cp.async.cg.shared.global [%0], [%1], 16;"
                 :: "r"(dst), "l"(src) : "memory");
}
__device__ __forceinline__ void ldsm4(uint32_t& r0, uint32_t& r1, uint32_t& r2,
                                      uint32_t& r3, uint32_t addr) {
    asm volatile("ldmatrix.sync.aligned.m8n8.x4.shared.b16 {%0,%1,%2,%3}, [%4];"
                 : "=r"(r0), "=r"(r1), "=r"(r2), "=r"(r3) : "r"(addr));
}
__device__ __forceinline__ void mma16816(float* d, const uint32_t* a,
                                         const uint32_t* b) {
    asm volatile(
        "mma.sync.aligned.m16n8k16.row.col.f32.bf16.bf16.f32 "
        "{%0,%1,%2,%3}, {%4,%5,%6,%7}, {%8,%9}, {%0,%1,%2,%3};"
        : "+f"(d[0]), "+f"(d[1]), "+f"(d[2]), "+f"(d[3])
        : "r"(a[0]), "r"(a[1]), "r"(a[2]), "r"(a[3]), "r"(b[0]), "r"(b[1]));
}
__device__ __forceinline__ uint32_t pack_hi(float a, float b) {
    __nv_bfloat162 h = __floats2bfloat162_rn(a, b);
    return *(uint32_t*)&h;
}

// ---------------------------------------------------------------------------
// K0a: fused weights -> transposed bf16 hi/lo (B-operand layout)
// ---------------------------------------------------------------------------
__global__ void fuse_weights_kernel(const float* __restrict__ W_self,
                                    const float* __restrict__ W_nb,
                                    const float* __restrict__ W_comb) {
    const int z = blockIdx.z;
    const float* __restrict__ Wx = z ? W_nb : W_self;
    __nv_bfloat16* __restrict__ oh = z ? g_BT_hi : g_AT_hi;
    __nv_bfloat16* __restrict__ ol = z ? g_BT_lo : g_AT_lo;
    const int woff = z * DIM;

    __shared__ float As[16][64];
    __shared__ float Bs[16][64];
    const int tid = threadIdx.x;
    const int tx = tid & 15, ty = tid >> 4;
    const int brow = blockIdx.y * 64, bcol = blockIdx.x * 64;
    const int a_m = tid >> 2, a_kc = (tid & 3) << 2;
    const int b_k = tid >> 4, b_n = (tid & 15) << 2;

    float acc[4][4] = {};
    for (int k0 = 0; k0 < DIM; k0 += 16) {
        float4 av = *(const float4*)&Wx[(brow + a_m) * DIM + k0 + a_kc];
        As[a_kc + 0][a_m] = av.x; As[a_kc + 1][a_m] = av.y;
        As[a_kc + 2][a_m] = av.z; As[a_kc + 3][a_m] = av.w;
        *(float4*)&Bs[b_k][b_n] =
            *(const float4*)&W_comb[(woff + k0 + b_k) * DIM + bcol + b_n];
        __syncthreads();
        #pragma unroll
        for (int k = 0; k < 16; k++) {
            float af[4], bf[4];
            *(float4*)af = *(const float4*)&As[k][ty * 4];
            *(float4*)bf = *(const float4*)&Bs[k][tx * 4];
            #pragma unroll
            for (int i = 0; i < 4; i++)
                #pragma unroll
                for (int j = 0; j < 4; j++) acc[i][j] += af[i] * bf[j];
        }
        __syncthreads();
    }
    // acc[i][j] = Out[k = brow+ty*4+i][n = bcol+tx*4+j]; store transposed [n][k]
    #pragma unroll
    for (int i = 0; i < 4; i++) {
        const int k = brow + ty * 4 + i;
        #pragma unroll
        for (int j = 0; j < 4; j++) {
            const int n = bcol + tx * 4 + j;
            float v = acc[i][j];
            __nv_bfloat16 h = __float2bfloat16(v);
            oh[n * DIM + k] = h;
            ol[n * DIM + k] = __float2bfloat16(v - __bfloat162float(h));
        }
    }
}

// ---------------------------------------------------------------------------
// K0b: fused bias
// ---------------------------------------------------------------------------
__global__ void fuse_bias_kernel(const float* __restrict__ b_self,
                                 const float* __restrict__ b_nb,
                                 const float* __restrict__ W_comb,
                                 const float* __restrict__ b_comb) {
    const int j = threadIdx.x;
    float s0 = b_comb[j], s1 = 0.f, s2 = 0.f, s3 = 0.f;
    #pragma unroll 4
    for (int k = 0; k < DIM; k += 2) {
        s0 += b_self[k] * W_comb[k * DIM + j];
        s1 += b_self[k + 1] * W_comb[(k + 1) * DIM + j];
        s2 += b_nb[k] * W_comb[(DIM + k) * DIM + j];
        s3 += b_nb[k + 1] * W_comb[(DIM + k + 1) * DIM + j];
    }
    g_c[j] = (s0 + s1) + (s2 + s3);
}

// ---------------------------------------------------------------------------
// K1: degree -> reciprocal, fused with adj -> bf16 mask conversion
// ---------------------------------------------------------------------------
__global__ void degree_mask_kernel(const int* __restrict__ adj) {
    const int row = blockIdx.x;
    const int4* __restrict__ p = (const int4*)(adj + (size_t)row * N_NODES);
    uint2* __restrict__ mrow = (uint2*)(g_mask + (size_t)row * N_NODES);
    int cnt = 0;
    for (int i = threadIdx.x; i < N_NODES / 4; i += blockDim.x) {
        int4 v = p[i];
        cnt += (v.x > 0) + (v.y > 0) + (v.z > 0) + (v.w > 0);
        uint2 o;
        o.x = (v.x > 0 ? 0x3F80u : 0u) | ((v.y > 0 ? 0x3F80u : 0u) << 16);
        o.y = (v.z > 0 ? 0x3F80u : 0u) | ((v.w > 0 ? 0x3F80u : 0u) << 16);
        mrow[i] = o;
    }
    #pragma unroll
    for (int o = 16; o; o >>= 1) cnt += __shfl_down_sync(0xffffffffu, cnt, o);
    __shared__ int wsum[8];
    if ((threadIdx.x & 31) == 0) wsum[threadIdx.x >> 5] = cnt;
    __syncthreads();
    if (threadIdx.x == 0) {
        int t = 0;
        #pragma unroll
        for (int w = 0; w < 8; w++) t += wsum[w];
        g_recip[row] = 1.0f / (float)max(t, 1);
    }
}

// ---------------------------------------------------------------------------
// K1b: x -> bf16 hi/lo, both transposed [feat][node] and row-major [node][feat]
// ---------------------------------------------------------------------------
__global__ void transpose_split_kernel(const float* __restrict__ x) {
    __shared__ float t[32][33];
    const int c0 = blockIdx.x * 32;   // feature dim
    const int r0 = blockIdx.y * 32;   // node dim
    const int tx = threadIdx.x, ty = threadIdx.y;
    #pragma unroll
    for (int i = 0; i < 4; i++) {
        const size_t gi = (size_t)(r0 + ty + 8 * i) * DIM + c0 + tx;
        float v = x[gi];
        t[ty + 8 * i][tx] = v;
        __nv_bfloat16 h = __float2bfloat16(v);
        g_x_hi[gi] = h;
        g_x_lo[gi] = __float2bfloat16(v - __bfloat162float(h));
    }
    __syncthreads();
    #pragma unroll
    for (int i = 0; i < 4; i++) {
        float v = t[tx][ty + 8 * i];
        __nv_bfloat16 h = __float2bfloat16(v);
        __nv_bfloat16 l = __float2bfloat16(v - __bfloat162float(h));
        size_t o = (size_t)(c0 + ty + 8 * i) * N_NODES + r0 + tx;
        g_xT_hi[o] = h;
        g_xT_lo[o] = l;
    }
}

// ---------------------------------------------------------------------------
// shared GEMM geometry
// ---------------------------------------------------------------------------
#define BK 32
#define PITCHB 80                 // 40 bf16 per smem row (conflict-free ldmatrix)
#define TILEB (128 * PITCHB)      // 10240 B per tile

// ---------------------------------------------------------------------------
// K2: agg = (mask @ x) * recip  via HMMA; epilogue stores bf16 hi/lo
// ---------------------------------------------------------------------------
#define STAGEB (3 * TILEB)        // A + Bh + Bl
#define AGG_SMEM (4 * STAGEB)     // 122880 B

__device__ __forceinline__ void issue_stage_agg(uint32_t sb, int slot, int k0,
                                                int brow, int bcol, int tid) {
    const uint32_t base = sb + slot * STAGEB;
    #pragma unroll
    for (int h = 0; h < 2; h++) {
        const int id = tid + h * 256;
        const int row = id >> 2, cc = id & 3;
        const uint32_t so = row * PITCHB + cc * 16;
        const size_t goA = (size_t)(brow + row) * N_NODES + k0 + cc * 8;
        const size_t goB = (size_t)(bcol + row) * N_NODES + k0 + cc * 8;
        cp16(base + so,             g_mask + goA);
        cp16(base + TILEB + so,     g_xT_hi + goB);
        cp16(base + 2 * TILEB + so, g_xT_lo + goB);
    }
    asm volatile("cp.async.commit_group;" ::: "memory");
}

__global__ void __launch_bounds__(256, 1) agg_mma_kernel() {
    extern __shared__ char smem[];
    const uint32_t sb = smem_u32(smem);
    const int tid = threadIdx.x;
    const int lane = tid & 31, w = tid >> 5;
    const int wm = w & 3, wn = w >> 2;
    const int brow = blockIdx.y * 128;
    const int bcol = blockIdx.x * 128;
    const int g = lane >> 3, r = lane & 7;

    const int NIT = N_NODES / BK;  // 256
    issue_stage_agg(sb, 0, 0, brow, bcol, tid);
    issue_stage_agg(sb, 1, BK, brow, bcol, tid);
    issue_stage_agg(sb, 2, 2 * BK, brow, bcol, tid);

    float acc[2][8][4] = {};

    for (int s = 0; s < NIT; s++) {
        asm volatile("cp.async.wait_group 2;" ::: "memory");
        __syncthreads();
        if (s + 3 < NIT)
            issue_stage_agg(sb, (s + 3) & 3, (s + 3) * BK, brow, bcol, tid);
        else
            asm volatile("cp.async.commit_group;" ::: "memory");

        const uint32_t sA  = sb + (s & 3) * STAGEB;
        const uint32_t sBh = sA + TILEB;
        const uint32_t sBl = sA + 2 * TILEB;

        #pragma unroll
        for (int ks = 0; ks < 2; ks++) {
            uint32_t a[2][4];
            #pragma unroll
            for (int mi = 0; mi < 2; mi++) {
                const uint32_t addr = sA +
                    (wm * 32 + mi * 16 + (g & 1) * 8 + r) * PITCHB +
                    ks * 32 + (g >> 1) * 16;
                ldsm4(a[mi][0], a[mi][1], a[mi][2], a[mi][3], addr);
            }
            uint32_t bh[8][2], bl[8][2];
            #pragma unroll
            for (int nj = 0; nj < 4; nj++) {
                const uint32_t roff =
                    (wn * 64 + nj * 16 + (g >> 1) * 8 + r) * PITCHB +
                    ks * 32 + (g & 1) * 16;
                uint32_t r0, r1, r2, r3;
                ldsm4(r0, r1, r2, r3, sBh + roff);
                bh[nj * 2][0] = r0; bh[nj * 2][1] = r1;
                bh[nj * 2 + 1][0] = r2; bh[nj * 2 + 1][1] = r3;
                ldsm4(r0, r1, r2, r3, sBl + roff);
                bl[nj * 2][0] = r0; bl[nj * 2][1] = r1;
                bl[nj * 2 + 1][0] = r2; bl[nj * 2 + 1][1] = r3;
            }
            #pragma unroll
            for (int mi = 0; mi < 2; mi++)
                #pragma unroll
                for (int ni = 0; ni < 8; ni++) {
                    mma16816(acc[mi][ni], a[mi], bh[ni]);
                    mma16816(acc[mi][ni], a[mi], bl[ni]);
                }
        }
    }
    asm volatile("cp.async.wait_group 0;" ::: "memory");

    // epilogue: scale by reciprocal degree, split to bf16 hi/lo
    #pragma unroll
    for (int mi = 0; mi < 2; mi++) {
        const int r0 = brow + wm * 32 + mi * 16 + (lane >> 2);
        const float rc0 = g_recip[r0];
        const float rc1 = g_recip[r0 + 8];
        #pragma unroll
        for (int ni = 0; ni < 8; ni++) {
            const int col = bcol + wn * 64 + ni * 8 + (lane & 3) * 2;
            float v0 = acc[mi][ni][0] * rc0, v1 = acc[mi][ni][1] * rc0;
            float v2 = acc[mi][ni][2] * rc1, v3 = acc[mi][ni][3] * rc1;
            float h0 = __bfloat162float(__float2bfloat16(v0));
            float h1 = __bfloat162float(__float2bfloat16(v1));
            float h2 = __bfloat162float(__float2bfloat16(v2));
            float h3 = __bfloat162float(__float2bfloat16(v3));
            const size_t o0 = ((size_t)r0 * DIM + col) >> 1;
            const size_t o1 = ((size_t)(r0 + 8) * DIM + col) >> 1;
            ((uint32_t*)g_agg_hi)[o0] = pack_hi(v0, v1);
            ((uint32_t*)g_agg_lo)[o0] = pack_hi(v0 - h0, v1 - h1);
            ((uint32_t*)g_agg_hi)[o1] = pack_hi(v2, v3);
            ((uint32_t*)g_agg_lo)[o1] = pack_hi(v2 - h2, v3 - h3);
        }
    }
}

// ---------------------------------------------------------------------------
// K3: out = relu(x@A + agg@B + c) via HMMA, hi/lo x hi/lo (3 products)
// 32 chunks: pass0 = x(16 chunks), pass1 = agg(16 chunks)
// ---------------------------------------------------------------------------
#define OSTAGEB (4 * TILEB)       // Ah + Al + Bh + Bl
#define OUT_SMEM (4 * OSTAGEB)    // 163840 B

__device__ __forceinline__ void issue_stage_out(uint32_t sb, int slot, int chunk,
                                                int brow, int bcol, int tid) {
    const int pass = chunk >> 4;
    const int k0 = (chunk & 15) * BK;
    const __nv_bfloat16* __restrict__ Ah = pass ? g_agg_hi : g_x_hi;
    const __nv_bfloat16* __restrict__ Al = pass ? g_agg_lo : g_x_lo;
    const __nv_bfloat16* __restrict__ Bh = pass ? g_BT_hi : g_AT_hi;
    const __nv_bfloat16* __restrict__ Bl = pass ? g_BT_lo : g_AT_lo;
    const uint32_t base = sb + slot * OSTAGEB;
    #pragma unroll
    for (int h = 0; h < 2; h++) {
        const int id = tid + h * 256;
        const int row = id >> 2, cc = id & 3;
        const uint32_t so = row * PITCHB + cc * 16;
        const size_t goA = (size_t)(brow + row) * DIM + k0 + cc * 8;
        const size_t goB = (size_t)(bcol + row) * DIM + k0 + cc * 8;
        cp16(base + so,             Ah + goA);
        cp16(base + TILEB + so,     Al + goA);
        cp16(base + 2 * TILEB + so, Bh + goB);
        cp16(base + 3 * TILEB + so, Bl + goB);
    }
    asm volatile("cp.async.commit_group;" ::: "memory");
}

__global__ void __launch_bounds__(256, 1) out_mma_kernel(float* __restrict__ out) {
    extern __shared__ char smem[];
    const uint32_t sb = smem_u32(smem);
    const int tid = threadIdx.x;
    const int lane = tid & 31, w = tid >> 5;
    const int wm = w & 3, wn = w >> 2;
    const int brow = blockIdx.y * 128;
    const int bcol = blockIdx.x * 128;
    const int g = lane >> 3, r = lane & 7;

    const int NIT = 32;
    issue_stage_out(sb, 0, 0, brow, bcol, tid);
    issue_stage_out(sb, 1, 1, brow, bcol, tid);
    issue_stage_out(sb, 2, 2, brow, bcol, tid);

    float acc[2][8][4] = {};

    for (int s = 0; s < NIT; s++) {
        asm volatile("cp.async.wait_group 2;" ::: "memory");
        __syncthreads();
        if (s + 3 < NIT)
            issue_stage_out(sb, (s + 3) & 3, s + 3, brow, bcol, tid);
        else
            asm volatile("cp.async.commit_group;" ::: "memory");

        const uint32_t sAh = sb + (s & 3) * OSTAGEB;
        const uint32_t sAl = sAh + TILEB;
        const uint32_t sBh = sAh + 2 * TILEB;
        const uint32_t sBl = sAh + 3 * TILEB;

        #pragma unroll
        for (int ks = 0; ks < 2; ks++) {
            uint32_t ah[2][4], al[2][4];
            #pragma unroll
            for (int mi = 0; mi < 2; mi++) {
                const uint32_t ro =
                    (wm * 32 + mi * 16 + (g & 1) * 8 + r) * PITCHB +
                    ks * 32 + (g >> 1) * 16;
                ldsm4(ah[mi][0], ah[mi][1], ah[mi][2], ah[mi][3], sAh + ro);
                ldsm4(al[mi][0], al[mi][1], al[mi][2], al[mi][3], sAl + ro);
            }
            uint32_t bh[8][2], bl[8][2];
            #pragma unroll
            for (int nj = 0; nj < 4; nj++) {
                const uint32_t roff =
                    (wn * 64 + nj * 16 + (g >> 1) * 8 + r) * PITCHB +
                    ks * 32 + (g & 1) * 16;
                uint32_t r0, r1, r2, r3;
                ldsm4(r0, r1, r2, r3, sBh + roff);
                bh[nj * 2][0] = r0; bh[nj * 2][1] = r1;
                bh[nj * 2 + 1][0] = r2; bh[nj * 2 + 1][1] = r3;
                ldsm4(r0, r1, r2, r3, sBl + roff);
                bl[nj * 2][0] = r0; bl[nj * 2][1] = r1;
                bl[nj * 2 + 1][0] = r2; bl[nj * 2 + 1][1] = r3;
            }
            #pragma unroll
            for (int mi = 0; mi < 2; mi++)
                #pragma unroll
                for (int ni = 0; ni < 8; ni++) {
                    mma16816(acc[mi][ni], ah[mi], bh[ni]);
                    mma16816(acc[mi][ni], al[mi], bh[ni]);
                    mma16816(acc[mi][ni], ah[mi], bl[ni]);
                }
        }
    }
    asm volatile("cp.async.wait_group 0;" ::: "memory");

    // epilogue: + bias, relu, store fp32
    #pragma unroll
    for (int mi = 0; mi < 2; mi++) {
        const int r0 = brow + wm * 32 + mi * 16 + (lane >> 2);
        #pragma unroll
        for (int ni = 0; ni < 8; ni++) {
            const int col = bcol + wn * 64 + ni * 8 + (lane & 3) * 2;
            const float c0 = g_c[col], c1 = g_c[col + 1];
            float2 v0 = make_float2(fmaxf(acc[mi][ni][0] + c0, 0.f),
                                    fmaxf(acc[mi][ni][1] + c1, 0.f));
            *(float2*)&out[(size_t)r0 * DIM + col] = v0;
            float2 v1 = make_float2(fmaxf(acc[mi][ni][2] + c0, 0.f),
                                    fmaxf(acc[mi][ni][3] + c1, 0.f));
            *(float2*)&out[(size_t)(r0 + 8) * DIM + col] = v1;
        }
    }
}

// ---------------------------------------------------------------------------
extern "C" void kernel_launch(void* const* d_in, const int* in_sizes, int n_in,
                              void* d_out, int out_size) {
    const float* x      = (const float*)d_in[0];
    const int*   adj    = (const int*)d_in[1];
    const float* W_self = (const float*)d_in[2];
    const float* b_self = (const float*)d_in[3];
    const float* W_nb   = (const float*)d_in[4];
    const float* b_nb   = (const float*)d_in[5];
    const float* W_comb = (const float*)d_in[6];
    const float* b_comb = (const float*)d_in[7];
    float* out = (float*)d_out;

    static bool attr_done = false;
    if (!attr_done) {
        cudaFuncSetAttribute(agg_mma_kernel,
                             cudaFuncAttributeMaxDynamicSharedMemorySize, AGG_SMEM);
        cudaFuncSetAttribute(out_mma_kernel,
                             cudaFuncAttributeMaxDynamicSharedMemorySize, OUT_SMEM);
        attr_done = true;
    }

    fuse_weights_kernel<<<dim3(8, 8, 2), 256>>>(W_self, W_nb, W_comb);
    fuse_bias_kernel<<<1, 512>>>(b_self, b_nb, W_comb, b_comb);
    degree_mask_kernel<<<N_NODES, 256>>>(adj);
    transpose_split_kernel<<<dim3(DIM / 32, N_NODES / 32), dim3(32, 8)>>>(x);
    agg_mma_kernel<<<dim3(4, 64), 256, AGG_SMEM>>>();
    out_mma_kernel<<<dim3(4, 64), 256, OUT_SMEM>>>(out);
}

// round 6
// speedup vs baseline: 2.9292x; 1.0468x over previous
#include <cuda_runtime.h>
#include <cuda_bf16.h>
#include <cstdint>

#define N_NODES 8192
#define DIM 512

// ---------------- scratch (__device__ globals; no allocs allowed) ----------
__device__ float g_c[DIM];                                      // fused bias
__device__ float g_recip[N_NODES];                              // 1/max(deg,1)
__device__ __align__(16) __nv_bfloat16 g_xT_hi[DIM * N_NODES];  // [feat][node]
__device__ __align__(16) __nv_bfloat16 g_xT_lo[DIM * N_NODES];
__device__ __align__(16) __nv_bfloat16 g_x_hi[N_NODES * DIM];   // [node][feat]
__device__ __align__(16) __nv_bfloat16 g_x_lo[N_NODES * DIM];
__device__ __align__(16) __nv_bfloat16 g_agg_hi[N_NODES * DIM]; // [node][feat]
__device__ __align__(16) __nv_bfloat16 g_agg_lo[N_NODES * DIM];
__device__ __align__(16) __nv_bfloat16 g_AT_hi[DIM * DIM];      // (W_self@Wt)^T
__device__ __align__(16) __nv_bfloat16 g_AT_lo[DIM * DIM];
__device__ __align__(16) __nv_bfloat16 g_BT_hi[DIM * DIM];      // (W_nb@Wb)^T
__device__ __align__(16) __nv_bfloat16 g_BT_lo[DIM * DIM];
__device__ __align__(16) __nv_bfloat16 g_mask[(size_t)N_NODES * N_NODES]; // 128 MB

// ---------------- PTX helpers (sm_80-era; legal on plain sm_103 target) ----
__device__ __forceinline__ uint32_t smem_u32(const void* p) {
    uint32_t a;
    asm("{ .reg .u64 t; cvta.to.shared.u64 t, %1; cvt.u32.u64 %0, t; }"
        : "=r"(a) : "l"(p));
    return a;
}
__device__ __forceinline__ void cp16(uint32_t dst, const void* src) {
    asm volatile("cp.async.cg.shared.global [%0], [%1], 16;"
                 :: "r"(dst), "l"(src) : "memory");
}
__device__ __forceinline__ void ldsm4(uint32_t& r0, uint32_t& r1, uint32_t& r2,
                                      uint32_t& r3, uint32_t addr) {
    asm volatile("ldmatrix.sync.aligned.m8n8.x4.shared.b16 {%0,%1,%2,%3}, [%4];"
                 : "=r"(r0), "=r"(r1), "=r"(r2), "=r"(r3) : "r"(addr));
}
__device__ __forceinline__ void mma16816(float* d, const uint32_t* a,
                                         const uint32_t* b) {
    asm volatile(
        "mma.sync.aligned.m16n8k16.row.col.f32.bf16.bf16.f32 "
        "{%0,%1,%2,%3}, {%4,%5,%6,%7}, {%8,%9}, {%0,%1,%2,%3};"
        : "+f"(d[0]), "+f"(d[1]), "+f"(d[2]), "+f"(d[3])
        : "r"(a[0]), "r"(a[1]), "r"(a[2]), "r"(a[3]), "r"(b[0]), "r"(b[1]));
}
__device__ __forceinline__ uint32_t pack_hi(float a, float b) {
    __nv_bfloat162 h = __floats2bfloat162_rn(a, b);
    return *(uint32_t*)&h;
}

// ---------------------------------------------------------------------------
// K0a: fused weights -> transposed bf16 hi/lo (B-operand layout)
// ---------------------------------------------------------------------------
__global__ void fuse_weights_kernel(const float* __restrict__ W_self,
                                    const float* __restrict__ W_nb,
                                    const float* __restrict__ W_comb) {
    const int z = blockIdx.z;
    const float* __restrict__ Wx = z ? W_nb : W_self;
    __nv_bfloat16* __restrict__ oh = z ? g_BT_hi : g_AT_hi;
    __nv_bfloat16* __restrict__ ol = z ? g_BT_lo : g_AT_lo;
    const int woff = z * DIM;

    __shared__ float As[16][64];
    __shared__ float Bs[16][64];
    const int tid = threadIdx.x;
    const int tx = tid & 15, ty = tid >> 4;
    const int brow = blockIdx.y * 64, bcol = blockIdx.x * 64;
    const int a_m = tid >> 2, a_kc = (tid & 3) << 2;
    const int b_k = tid >> 4, b_n = (tid & 15) << 2;

    float acc[4][4] = {};
    for (int k0 = 0; k0 < DIM; k0 += 16) {
        float4 av = *(const float4*)&Wx[(brow + a_m) * DIM + k0 + a_kc];
        As[a_kc + 0][a_m] = av.x; As[a_kc + 1][a_m] = av.y;
        As[a_kc + 2][a_m] = av.z; As[a_kc + 3][a_m] = av.w;
        *(float4*)&Bs[b_k][b_n] =
            *(const float4*)&W_comb[(woff + k0 + b_k) * DIM + bcol + b_n];
        __syncthreads();
        #pragma unroll
        for (int k = 0; k < 16; k++) {
            float af[4], bf[4];
            *(float4*)af = *(const float4*)&As[k][ty * 4];
            *(float4*)bf = *(const float4*)&Bs[k][tx * 4];
            #pragma unroll
            for (int i = 0; i < 4; i++)
                #pragma unroll
                for (int j = 0; j < 4; j++) acc[i][j] += af[i] * bf[j];
        }
        __syncthreads();
    }
    #pragma unroll
    for (int i = 0; i < 4; i++) {
        const int k = brow + ty * 4 + i;
        #pragma unroll
        for (int j = 0; j < 4; j++) {
            const int n = bcol + tx * 4 + j;
            float v = acc[i][j];
            __nv_bfloat16 h = __float2bfloat16(v);
            oh[n * DIM + k] = h;
            ol[n * DIM + k] = __float2bfloat16(v - __bfloat162float(h));
        }
    }
}

// ---------------------------------------------------------------------------
// K0b: fused bias
// ---------------------------------------------------------------------------
__global__ void fuse_bias_kernel(const float* __restrict__ b_self,
                                 const float* __restrict__ b_nb,
                                 const float* __restrict__ W_comb,
                                 const float* __restrict__ b_comb) {
    const int j = threadIdx.x;
    float s0 = b_comb[j], s1 = 0.f, s2 = 0.f, s3 = 0.f;
    #pragma unroll 4
    for (int k = 0; k < DIM; k += 2) {
        s0 += b_self[k] * W_comb[k * DIM + j];
        s1 += b_self[k + 1] * W_comb[(k + 1) * DIM + j];
        s2 += b_nb[k] * W_comb[(DIM + k) * DIM + j];
        s3 += b_nb[k + 1] * W_comb[(DIM + k + 1) * DIM + j];
    }
    g_c[j] = (s0 + s1) + (s2 + s3);
}

// ---------------------------------------------------------------------------
// K1: degree -> reciprocal, fused with adj -> bf16 mask conversion
// ---------------------------------------------------------------------------
__global__ void degree_mask_kernel(const int* __restrict__ adj) {
    const int row = blockIdx.x;
    const int4* __restrict__ p = (const int4*)(adj + (size_t)row * N_NODES);
    uint2* __restrict__ mrow = (uint2*)(g_mask + (size_t)row * N_NODES);
    int cnt = 0;
    for (int i = threadIdx.x; i < N_NODES / 4; i += blockDim.x) {
        int4 v = p[i];
        cnt += (v.x > 0) + (v.y > 0) + (v.z > 0) + (v.w > 0);
        uint2 o;
        o.x = (v.x > 0 ? 0x3F80u : 0u) | ((v.y > 0 ? 0x3F80u : 0u) << 16);
        o.y = (v.z > 0 ? 0x3F80u : 0u) | ((v.w > 0 ? 0x3F80u : 0u) << 16);
        mrow[i] = o;
    }
    #pragma unroll
    for (int o = 16; o; o >>= 1) cnt += __shfl_down_sync(0xffffffffu, cnt, o);
    __shared__ int wsum[8];
    if ((threadIdx.x & 31) == 0) wsum[threadIdx.x >> 5] = cnt;
    __syncthreads();
    if (threadIdx.x == 0) {
        int t = 0;
        #pragma unroll
        for (int w = 0; w < 8; w++) t += wsum[w];
        g_recip[row] = 1.0f / (float)max(t, 1);
    }
}

// ---------------------------------------------------------------------------
// K1b: x -> bf16 hi/lo, transposed [feat][node] and row-major [node][feat]
// ---------------------------------------------------------------------------
__global__ void transpose_split_kernel(const float* __restrict__ x) {
    __shared__ float t[32][33];
    const int c0 = blockIdx.x * 32;
    const int r0 = blockIdx.y * 32;
    const int tx = threadIdx.x, ty = threadIdx.y;
    #pragma unroll
    for (int i = 0; i < 4; i++) {
        const size_t gi = (size_t)(r0 + ty + 8 * i) * DIM + c0 + tx;
        float v = x[gi];
        t[ty + 8 * i][tx] = v;
        __nv_bfloat16 h = __float2bfloat16(v);
        g_x_hi[gi] = h;
        g_x_lo[gi] = __float2bfloat16(v - __bfloat162float(h));
    }
    __syncthreads();
    #pragma unroll
    for (int i = 0; i < 4; i++) {
        float v = t[tx][ty + 8 * i];
        __nv_bfloat16 h = __float2bfloat16(v);
        __nv_bfloat16 l = __float2bfloat16(v - __bfloat162float(h));
        size_t o = (size_t)(c0 + ty + 8 * i) * N_NODES + r0 + tx;
        g_xT_hi[o] = h;
        g_xT_lo[o] = l;
    }
}

// ---------------------------------------------------------------------------
// shared GEMM geometry
// ---------------------------------------------------------------------------
#define BK 32
#define PITCHB 80                 // 40 bf16 per smem row (conflict-free ldmatrix)
#define TILEB (128 * PITCHB)      // 10240 B per tile

// ---------------------------------------------------------------------------
// K2: agg = (mask @ x) * recip  via HMMA; 3-stage ring, 2 CTAs/SM
// ---------------------------------------------------------------------------
#define STAGEB (3 * TILEB)        // A + Bh + Bl = 30720 B
#define AGG_SMEM (3 * STAGEB)     // 92160 B -> 2 CTAs/SM

__device__ __forceinline__ void issue_stage_agg(uint32_t sb, int slot, int k0,
                                                int brow, int bcol, int tid) {
    const uint32_t base = sb + slot * STAGEB;
    #pragma unroll
    for (int h = 0; h < 2; h++) {
        const int id = tid + h * 256;
        const int row = id >> 2, cc = id & 3;
        const uint32_t so = row * PITCHB + cc * 16;
        const size_t goA = (size_t)(brow + row) * N_NODES + k0 + cc * 8;
        const size_t goB = (size_t)(bcol + row) * N_NODES + k0 + cc * 8;
        cp16(base + so,             g_mask + goA);
        cp16(base + TILEB + so,     g_xT_hi + goB);
        cp16(base + 2 * TILEB + so, g_xT_lo + goB);
    }
    asm volatile("cp.async.commit_group;" ::: "memory");
}

__global__ void __launch_bounds__(256, 2) agg_mma_kernel() {
    extern __shared__ char smem[];
    const uint32_t sb = smem_u32(smem);
    const int tid = threadIdx.x;
    const int lane = tid & 31, w = tid >> 5;
    const int wm = w & 3, wn = w >> 2;
    const int brow = blockIdx.y * 128;
    const int bcol = blockIdx.x * 128;
    const int g = lane >> 3, r = lane & 7;

    const int NIT = N_NODES / BK;  // 256
    issue_stage_agg(sb, 0, 0, brow, bcol, tid);
    issue_stage_agg(sb, 1, BK, brow, bcol, tid);
    issue_stage_agg(sb, 2, 2 * BK, brow, bcol, tid);

    float acc[2][8][4] = {};
    int slot = 0;

    for (int s = 0; s < NIT; s++) {
        asm volatile("cp.async.wait_group 2;" ::: "memory");
        __syncthreads();

        const uint32_t sA  = sb + slot * STAGEB;
        const uint32_t sBh = sA + TILEB;
        const uint32_t sBl = sA + 2 * TILEB;

        #pragma unroll
        for (int ks = 0; ks < 2; ks++) {
            uint32_t a[2][4];
            #pragma unroll
            for (int mi = 0; mi < 2; mi++) {
                const uint32_t addr = sA +
                    (wm * 32 + mi * 16 + (g & 1) * 8 + r) * PITCHB +
                    ks * 32 + (g >> 1) * 16;
                ldsm4(a[mi][0], a[mi][1], a[mi][2], a[mi][3], addr);
            }
            uint32_t bh[8][2], bl[8][2];
            #pragma unroll
            for (int nj = 0; nj < 4; nj++) {
                const uint32_t roff =
                    (wn * 64 + nj * 16 + (g >> 1) * 8 + r) * PITCHB +
                    ks * 32 + (g & 1) * 16;
                uint32_t r0, r1, r2, r3;
                ldsm4(r0, r1, r2, r3, sBh + roff);
                bh[nj * 2][0] = r0; bh[nj * 2][1] = r1;
                bh[nj * 2 + 1][0] = r2; bh[nj * 2 + 1][1] = r3;
                ldsm4(r0, r1, r2, r3, sBl + roff);
                bl[nj * 2][0] = r0; bl[nj * 2][1] = r1;
                bl[nj * 2 + 1][0] = r2; bl[nj * 2 + 1][1] = r3;
            }
            #pragma unroll
            for (int mi = 0; mi < 2; mi++)
                #pragma unroll
                for (int ni = 0; ni < 8; ni++) {
                    mma16816(acc[mi][ni], a[mi], bh[ni]);
                    mma16816(acc[mi][ni], a[mi], bl[ni]);
                }
        }
        __syncthreads();   // all warps done reading this slot
        if (s + 3 < NIT)
            issue_stage_agg(sb, slot, (s + 3) * BK, brow, bcol, tid);
        else
            asm volatile("cp.async.commit_group;" ::: "memory");
        slot = (slot == 2) ? 0 : slot + 1;
    }
    asm volatile("cp.async.wait_group 0;" ::: "memory");

    // epilogue: scale by reciprocal degree, split to bf16 hi/lo
    #pragma unroll
    for (int mi = 0; mi < 2; mi++) {
        const int r0 = brow + wm * 32 + mi * 16 + (lane >> 2);
        const float rc0 = g_recip[r0];
        const float rc1 = g_recip[r0 + 8];
        #pragma unroll
        for (int ni = 0; ni < 8; ni++) {
            const int col = bcol + wn * 64 + ni * 8 + (lane & 3) * 2;
            float v0 = acc[mi][ni][0] * rc0, v1 = acc[mi][ni][1] * rc0;
            float v2 = acc[mi][ni][2] * rc1, v3 = acc[mi][ni][3] * rc1;
            float h0 = __bfloat162float(__float2bfloat16(v0));
            float h1 = __bfloat162float(__float2bfloat16(v1));
            float h2 = __bfloat162float(__float2bfloat16(v2));
            float h3 = __bfloat162float(__float2bfloat16(v3));
            const size_t o0 = ((size_t)r0 * DIM + col) >> 1;
            const size_t o1 = ((size_t)(r0 + 8) * DIM + col) >> 1;
            ((uint32_t*)g_agg_hi)[o0] = pack_hi(v0, v1);
            ((uint32_t*)g_agg_lo)[o0] = pack_hi(v0 - h0, v1 - h1);
            ((uint32_t*)g_agg_hi)[o1] = pack_hi(v2, v3);
            ((uint32_t*)g_agg_lo)[o1] = pack_hi(v2 - h2, v3 - h3);
        }
    }
}

// ---------------------------------------------------------------------------
// K3: out = relu(x@A + agg@B + c) via HMMA, 2-stage ring, 2 CTAs/SM
// ---------------------------------------------------------------------------
#define OSTAGEB (4 * TILEB)       // Ah + Al + Bh + Bl = 40960 B
#define OUT_SMEM (2 * OSTAGEB)    // 81920 B -> 2 CTAs/SM

__device__ __forceinline__ void issue_stage_out(uint32_t sb, int slot, int chunk,
                                                int brow, int bcol, int tid) {
    const int pass = chunk >> 4;
    const int k0 = (chunk & 15) * BK;
    const __nv_bfloat16* __restrict__ Ah = pass ? g_agg_hi : g_x_hi;
    const __nv_bfloat16* __restrict__ Al = pass ? g_agg_lo : g_x_lo;
    const __nv_bfloat16* __restrict__ Bh = pass ? g_BT_hi : g_AT_hi;
    const __nv_bfloat16* __restrict__ Bl = pass ? g_BT_lo : g_AT_lo;
    const uint32_t base = sb + slot * OSTAGEB;
    #pragma unroll
    for (int h = 0; h < 2; h++) {
        const int id = tid + h * 256;
        const int row = id >> 2, cc = id & 3;
        const uint32_t so = row * PITCHB + cc * 16;
        const size_t goA = (size_t)(brow + row) * DIM + k0 + cc * 8;
        const size_t goB = (size_t)(bcol + row) * DIM + k0 + cc * 8;
        cp16(base + so,             Ah + goA);
        cp16(base + TILEB + so,     Al + goA);
        cp16(base + 2 * TILEB + so, Bh + goB);
        cp16(base + 3 * TILEB + so, Bl + goB);
    }
    asm volatile("cp.async.commit_group;" ::: "memory");
}

__global__ void __launch_bounds__(256, 2) out_mma_kernel(float* __restrict__ out) {
    extern __shared__ char smem[];
    const uint32_t sb = smem_u32(smem);
    const int tid = threadIdx.x;
    const int lane = tid & 31, w = tid >> 5;
    const int wm = w & 3, wn = w >> 2;
    const int brow = blockIdx.y * 128;
    const int bcol = blockIdx.x * 128;
    const int g = lane >> 3, r = lane & 7;

    const int NIT = 32;
    issue_stage_out(sb, 0, 0, brow, bcol, tid);
    issue_stage_out(sb, 1, 1, brow, bcol, tid);

    float acc[2][8][4] = {};
    int slot = 0;

    for (int s = 0; s < NIT; s++) {
        asm volatile("cp.async.wait_group 1;" ::: "memory");
        __syncthreads();

        const uint32_t sAh = sb + slot * OSTAGEB;
        const uint32_t sAl = sAh + TILEB;
        const uint32_t sBh = sAh + 2 * TILEB;
        const uint32_t sBl = sAh + 3 * TILEB;

        #pragma unroll
        for (int ks = 0; ks < 2; ks++) {
            uint32_t ah[2][4], al[2][4];
            #pragma unroll
            for (int mi = 0; mi < 2; mi++) {
                const uint32_t ro =
                    (wm * 32 + mi * 16 + (g & 1) * 8 + r) * PITCHB +
                    ks * 32 + (g >> 1) * 16;
                ldsm4(ah[mi][0], ah[mi][1], ah[mi][2], ah[mi][3], sAh + ro);
                ldsm4(al[mi][0], al[mi][1], al[mi][2], al[mi][3], sAl + ro);
            }
            uint32_t bh[8][2], bl[8][2];
            #pragma unroll
            for (int nj = 0; nj < 4; nj++) {
                const uint32_t roff =
                    (wn * 64 + nj * 16 + (g >> 1) * 8 + r) * PITCHB +
                    ks * 32 + (g & 1) * 16;
                uint32_t r0, r1, r2, r3;
                ldsm4(r0, r1, r2, r3, sBh + roff);
                bh[nj * 2][0] = r0; bh[nj * 2][1] = r1;
                bh[nj * 2 + 1][0] = r2; bh[nj * 2 + 1][1] = r3;
                ldsm4(r0, r1, r2, r3, sBl + roff);
                bl[nj * 2][0] = r0; bl[nj * 2][1] = r1;
                bl[nj * 2 + 1][0] = r2; bl[nj * 2 + 1][1] = r3;
            }
            #pragma unroll
            for (int mi = 0; mi < 2; mi++)
                #pragma unroll
                for (int ni = 0; ni < 8; ni++) {
                    mma16816(acc[mi][ni], ah[mi], bh[ni]);
                    mma16816(acc[mi][ni], al[mi], bh[ni]);
                    mma16816(acc[mi][ni], ah[mi], bl[ni]);
                }
        }
        __syncthreads();
        if (s + 2 < NIT)
            issue_stage_out(sb, slot, s + 2, brow, bcol, tid);
        else
            asm volatile("cp.async.commit_group;" ::: "memory");
        slot ^= 1;
    }
    asm volatile("cp.async.wait_group 0;" ::: "memory");

    // epilogue: + bias, relu, store fp32
    #pragma unroll
    for (int mi = 0; mi < 2; mi++) {
        const int r0 = brow + wm * 32 + mi * 16 + (lane >> 2);
        #pragma unroll
        for (int ni = 0; ni < 8; ni++) {
            const int col = bcol + wn * 64 + ni * 8 + (lane & 3) * 2;
            const float c0 = g_c[col], c1 = g_c[col + 1];
            float2 v0 = make_float2(fmaxf(acc[mi][ni][0] + c0, 0.f),
                                    fmaxf(acc[mi][ni][1] + c1, 0.f));
            *(float2*)&out[(size_t)r0 * DIM + col] = v0;
            float2 v1 = make_float2(fmaxf(acc[mi][ni][2] + c0, 0.f),
                                    fmaxf(acc[mi][ni][3] + c1, 0.f));
            *(float2*)&out[(size_t)(r0 + 8) * DIM + col] = v1;
        }
    }
}

// ---------------------------------------------------------------------------
extern "C" void kernel_launch(void* const* d_in, const int* in_sizes, int n_in,
                              void* d_out, int out_size) {
    const float* x      = (const float*)d_in[0];
    const int*   adj    = (const int*)d_in[1];
    const float* W_self = (const float*)d_in[2];
    const float* b_self = (const float*)d_in[3];
    const float* W_nb   = (const float*)d_in[4];
    const float* b_nb   = (const float*)d_in[5];
    const float* W_comb = (const float*)d_in[6];
    const float* b_comb = (const float*)d_in[7];
    float* out = (float*)d_out;

    static bool attr_done = false;
    if (!attr_done) {
        cudaFuncSetAttribute(agg_mma_kernel,
                             cudaFuncAttributeMaxDynamicSharedMemorySize, AGG_SMEM);
        cudaFuncSetAttribute(out_mma_kernel,
                             cudaFuncAttributeMaxDynamicSharedMemorySize, OUT_SMEM);
        attr_done = true;
    }

    fuse_weights_kernel<<<dim3(8, 8, 2), 256>>>(W_self, W_nb, W_comb);
    fuse_bias_kernel<<<1, 512>>>(b_self, b_nb, W_comb, b_comb);
    degree_mask_kernel<<<N_NODES, 256>>>(adj);
    transpose_split_kernel<<<dim3(DIM / 32, N_NODES / 32), dim3(32, 8)>>>(x);
    agg_mma_kernel<<<dim3(4, 64), 256, AGG_SMEM>>>();
    out_mma_kernel<<<dim3(4, 64), 256, OUT_SMEM>>>(out);
}